// round 2
// baseline (speedup 1.0000x reference)
#include <cuda_runtime.h>

// base = 3.0 + 0.7*5.0 = 6.5 ; i_dr = 6.5, i_mr = 4.55
// I_dr = 6.5 - 0.5 + 0.5*n = 6.0 + 0.5*n
// I_mr = 4.55 - 1.0 + 0.5*n = 3.55 + 0.5*n

#define N_DR 6000000
#define N_MR 2000000
#define TPB 256
#define BLOCKS_DR ((N_DR / 4 + TPB - 1) / TPB)   // 5860
#define BLOCKS_MR ((N_MR / 4 + TPB - 1) / TPB)   // 1954
#define BLOCKS_TOTAL (BLOCKS_DR + BLOCKS_MR)     // 7814

__device__ float g_part[BLOCKS_TOTAL];

__device__ __forceinline__ void izhi_step(float& v, float& u, float& r,
                                          float nz, float ibase) {
    float I = ibase + 0.5f * nz;
    v = v + (0.04f * v * v + 5.0f * v + 140.0f - u + I);
    u = u + 0.02f * (0.2f * v - u);
    bool s = (v >= 30.0f);
    float sf = s ? 1.0f : 0.0f;
    if (s) { v = -65.0f; u += 8.0f; }
    r = 0.9f * r + 0.1f * sf;
}

__global__ __launch_bounds__(TPB)
void izhi_fused_kernel(const float* __restrict__ noise_dr,
                       const float* __restrict__ v_dr,
                       const float* __restrict__ u_dr,
                       const float* __restrict__ r_dr,
                       const float* __restrict__ noise_mr,
                       const float* __restrict__ v_mr,
                       const float* __restrict__ u_mr,
                       const float* __restrict__ r_mr) {
    bool is_dr = (blockIdx.x < BLOCKS_DR);
    int lblk = is_dr ? blockIdx.x : (blockIdx.x - BLOCKS_DR);
    int n = is_dr ? N_DR : N_MR;
    const float* noise = is_dr ? noise_dr : noise_mr;
    const float* v0 = is_dr ? v_dr : v_mr;
    const float* u0 = is_dr ? u_dr : u_mr;
    const float* r0 = is_dr ? r_dr : r_mr;
    const float ibase = is_dr ? 6.0f : 3.55f;

    int i = (lblk * TPB + threadIdx.x) * 4;

    float local = 0.0f;
    if (i < n) {
        float4 v = __ldcs(reinterpret_cast<const float4*>(v0 + i));
        float4 u = __ldcs(reinterpret_cast<const float4*>(u0 + i));
        float4 r = __ldcs(reinterpret_cast<const float4*>(r0 + i));

#pragma unroll
        for (int t = 0; t < 20; t++) {
            float4 nz = __ldcs(reinterpret_cast<const float4*>(
                noise + (size_t)t * (size_t)n + i));
            izhi_step(v.x, u.x, r.x, nz.x, ibase);
            izhi_step(v.y, u.y, r.y, nz.y, ibase);
            izhi_step(v.z, u.z, r.z, nz.z, ibase);
            izhi_step(v.w, u.w, r.w, nz.w, ibase);
        }
        local = (r.x + r.y) + (r.z + r.w);
    }

    // Warp reduce
#pragma unroll
    for (int off = 16; off > 0; off >>= 1)
        local += __shfl_down_sync(0xFFFFFFFFu, local, off);

    __shared__ float warp_sums[TPB / 32];
    int lane = threadIdx.x & 31;
    int wid = threadIdx.x >> 5;
    if (lane == 0) warp_sums[wid] = local;
    __syncthreads();
    if (wid == 0) {
        float s = (lane < TPB / 32) ? warp_sums[lane] : 0.0f;
#pragma unroll
        for (int off = 4; off > 0; off >>= 1)
            s += __shfl_down_sync(0xFFFFFFFFu, s, off);
        if (lane == 0) g_part[blockIdx.x] = s;
    }
}

__global__ __launch_bounds__(1024)
void finalize_kernel(float* out) {
    double sdr = 0.0, smr = 0.0;
    for (int idx = threadIdx.x; idx < BLOCKS_TOTAL; idx += 1024) {
        float p = g_part[idx];
        if (idx < BLOCKS_DR) sdr += (double)p;
        else                 smr += (double)p;
    }
    // reduce across warp
#pragma unroll
    for (int off = 16; off > 0; off >>= 1) {
        sdr += __shfl_down_sync(0xFFFFFFFFu, sdr, off);
        smr += __shfl_down_sync(0xFFFFFFFFu, smr, off);
    }
    __shared__ double sh_dr[32], sh_mr[32];
    int lane = threadIdx.x & 31;
    int wid = threadIdx.x >> 5;
    if (lane == 0) { sh_dr[wid] = sdr; sh_mr[wid] = smr; }
    __syncthreads();
    if (wid == 0) {
        sdr = (lane < 32) ? sh_dr[lane] : 0.0;
        smr = (lane < 32) ? sh_mr[lane] : 0.0;
#pragma unroll
        for (int off = 16; off > 0; off >>= 1) {
            sdr += __shfl_down_sync(0xFFFFFFFFu, sdr, off);
            smr += __shfl_down_sync(0xFFFFFFFFu, smr, off);
        }
        if (lane == 0) {
            float dr_mean = (float)(sdr / (double)N_DR);
            float mr_mean = (float)(smr / (double)N_MR);
            float raw = fminf(fmaxf(dr_mean * 8.0f, 0.0f), 1.0f);
            float ema = 0.9f * 0.5f + 0.1f * raw;
            float ht5 = fminf(fmaxf(ema, 0.05f), 0.95f);
            out[0] = ht5;
            out[1] = dr_mean;
            out[2] = mr_mean;
            out[3] = 1.0f - 0.3f * ht5;
            out[4] = ht5;
        }
    }
}

extern "C" void kernel_launch(void* const* d_in, const int* in_sizes, int n_in,
                              void* d_out, int out_size) {
    const float* noise_dr = (const float*)d_in[0];
    const float* noise_mr = (const float*)d_in[1];
    const float* v_dr = (const float*)d_in[2];
    const float* u_dr = (const float*)d_in[3];
    const float* r_dr = (const float*)d_in[4];
    const float* v_mr = (const float*)d_in[5];
    const float* u_mr = (const float*)d_in[6];
    const float* r_mr = (const float*)d_in[7];

    izhi_fused_kernel<<<BLOCKS_TOTAL, TPB>>>(
        noise_dr, v_dr, u_dr, r_dr, noise_mr, v_mr, u_mr, r_mr);

    finalize_kernel<<<1, 1024>>>((float*)d_out);
}

// round 4
// speedup vs baseline: 1.0543x; 1.0543x over previous
#include <cuda_runtime.h>

// base = 3.0 + 0.7*5.0 = 6.5 ; i_dr = 6.5, i_mr = 4.55
// I_dr = 6.5 - 0.5 + 0.5*n = 6.0 + 0.5*n
// I_mr = 4.55 - 1.0 + 0.5*n = 3.55 + 0.5*n

#define N_DR 6000000
#define N_MR 2000000
#define TPB 256
#define BLOCKS_DR ((N_DR / 4 + TPB - 1) / TPB)   // 5860
#define BLOCKS_MR ((N_MR / 4 + TPB - 1) / TPB)   // 1954
#define BLOCKS_TOTAL (BLOCKS_DR + BLOCKS_MR)     // 7814

__device__ double g_sum_dr = 0.0;
__device__ double g_sum_mr = 0.0;
__device__ unsigned int g_count = 0;

__device__ __forceinline__ void izhi_step(float& v, float& u, float& r,
                                          float nz, float ibase) {
    float I = ibase + 0.5f * nz;
    v = v + (0.04f * v * v + 5.0f * v + 140.0f - u + I);
    u = u + 0.02f * (0.2f * v - u);
    bool s = (v >= 30.0f);
    float sf = s ? 1.0f : 0.0f;
    if (s) { v = -65.0f; u += 8.0f; }
    r = 0.9f * r + 0.1f * sf;
}

__global__ __launch_bounds__(TPB)
void izhi_fused_kernel(const float* __restrict__ noise_dr,
                       const float* __restrict__ v_dr,
                       const float* __restrict__ u_dr,
                       const float* __restrict__ r_dr,
                       const float* __restrict__ noise_mr,
                       const float* __restrict__ v_mr,
                       const float* __restrict__ u_mr,
                       const float* __restrict__ r_mr,
                       float* __restrict__ out) {
    bool is_dr = (blockIdx.x < BLOCKS_DR);
    int lblk = is_dr ? blockIdx.x : (blockIdx.x - BLOCKS_DR);
    int n = is_dr ? N_DR : N_MR;
    const float* noise = is_dr ? noise_dr : noise_mr;
    const float* v0 = is_dr ? v_dr : v_mr;
    const float* u0 = is_dr ? u_dr : u_mr;
    const float* r0 = is_dr ? r_dr : r_mr;
    const float ibase = is_dr ? 6.0f : 3.55f;

    int i = (lblk * TPB + threadIdx.x) * 4;

    float local = 0.0f;
    if (i < n) {
        float4 v = __ldcs(reinterpret_cast<const float4*>(v0 + i));
        float4 u = __ldcs(reinterpret_cast<const float4*>(u0 + i));
        float4 r = __ldcs(reinterpret_cast<const float4*>(r0 + i));

#pragma unroll
        for (int t = 0; t < 20; t++) {
            float4 nz = __ldcs(reinterpret_cast<const float4*>(
                noise + (size_t)t * (size_t)n + i));
            izhi_step(v.x, u.x, r.x, nz.x, ibase);
            izhi_step(v.y, u.y, r.y, nz.y, ibase);
            izhi_step(v.z, u.z, r.z, nz.z, ibase);
            izhi_step(v.w, u.w, r.w, nz.w, ibase);
        }
        local = (r.x + r.y) + (r.z + r.w);
    }

    // Warp reduce
#pragma unroll
    for (int off = 16; off > 0; off >>= 1)
        local += __shfl_down_sync(0xFFFFFFFFu, local, off);

    __shared__ float warp_sums[TPB / 32];
    __shared__ bool is_last;
    int lane = threadIdx.x & 31;
    int wid = threadIdx.x >> 5;
    if (lane == 0) warp_sums[wid] = local;
    __syncthreads();

    if (threadIdx.x == 0) {
        float s = 0.0f;
#pragma unroll
        for (int w = 0; w < TPB / 32; w++) s += warp_sums[w];

        if (is_dr) atomicAdd(&g_sum_dr, (double)s);
        else       atomicAdd(&g_sum_mr, (double)s);
        __threadfence();
        unsigned int done = atomicAdd(&g_count, 1u);
        is_last = (done == (unsigned int)(BLOCKS_TOTAL - 1));
    }
    __syncthreads();

    // Last block to finish computes the output and resets accumulators
    // for the next (graph-replayed) launch.
    if (is_last && threadIdx.x == 0) {
        __threadfence();
        double sdr = *((volatile double*)&g_sum_dr);
        double smr = *((volatile double*)&g_sum_mr);

        float dr_mean = (float)(sdr / (double)N_DR);
        float mr_mean = (float)(smr / (double)N_MR);
        float raw = fminf(fmaxf(dr_mean * 8.0f, 0.0f), 1.0f);
        float ema = 0.9f * 0.5f + 0.1f * raw;
        float ht5 = fminf(fmaxf(ema, 0.05f), 0.95f);
        out[0] = ht5;
        out[1] = dr_mean;
        out[2] = mr_mean;
        out[3] = 1.0f - 0.3f * ht5;
        out[4] = ht5;

        // Reset for next launch (visible at next kernel-launch boundary).
        g_sum_dr = 0.0;
        g_sum_mr = 0.0;
        g_count = 0;
        __threadfence();
    }
}

extern "C" void kernel_launch(void* const* d_in, const int* in_sizes, int n_in,
                              void* d_out, int out_size) {
    const float* noise_dr = (const float*)d_in[0];
    const float* noise_mr = (const float*)d_in[1];
    const float* v_dr = (const float*)d_in[2];
    const float* u_dr = (const float*)d_in[3];
    const float* r_dr = (const float*)d_in[4];
    const float* v_mr = (const float*)d_in[5];
    const float* u_mr = (const float*)d_in[6];
    const float* r_mr = (const float*)d_in[7];

    izhi_fused_kernel<<<BLOCKS_TOTAL, TPB>>>(
        noise_dr, v_dr, u_dr, r_dr, noise_mr, v_mr, u_mr, r_mr,
        (float*)d_out);
}